// round 11
// baseline (speedup 1.0000x reference)
#include <cuda_runtime.h>
#include <cstdint>

// Problem constants
#define B_DIM   8192
#define IN_DIM  256
#define OUT_DIM 256
#define MV      8

// Tiling: CTA = 64 b (32 bpairs) x 64 i, 128 threads (tx16 x ty8)
// per thread: 4 bpairs x 4 i, i = {2tx,2tx+1, 2tx+32,2tx+33}  (W as LDS.128 pairs)
// 2 CTAs/SM; chunk-level LDG prefetch + j-level X register pipeline;
// W loaded once per j as 6 conflict-floor LDS.128.
#define MT      64
#define IT      64
#define KJ      8
#define NCH     (IN_DIM / KJ)   // 32
#define XPAD    36
#define NTHR    128

typedef unsigned long long u64;

__device__ __forceinline__ u64 pack2(float lo, float hi) {
    u64 r; asm("mov.b64 %0, {%1, %2};" : "=l"(r) : "f"(lo), "f"(hi)); return r;
}
__device__ __forceinline__ u64 fma2(u64 a, u64 b, u64 c) {
    u64 d; asm("fma.rn.f32x2 %0, %1, %2, %3;" : "=l"(d) : "l"(a), "l"(b), "l"(c)); return d;
}
__device__ __forceinline__ void unpack2(u64 v, float& lo, float& hi) {
    asm("mov.b64 {%0, %1}, %2;" : "=f"(lo), "=f"(hi) : "l"(v));
}

// y[b,i,0] = bias[i,0] + sum_j x0*w0 + x1*w1 + x2*w2
// y[b,i,4] = bias[i,4] + sum_j x1*w2 - x2*w1 + x4*w0
__global__ void __launch_bounds__(NTHR, 2)
ga_mv_kernel(const float* __restrict__ x,
             const float* __restrict__ w,
             const float* __restrict__ bias,
             float* __restrict__ out)
{
    __shared__ u64 Xs[2][KJ][5][XPAD];   // x0,x1,x2,x4,-x2 as {b even, b odd}
    __shared__ u64 Ws[2][3][KJ][IT];     // w0,w1,w2 duplicated {w,w}

    const int tid   = threadIdx.x;
    const int tx    = tid & 15;
    const int ty    = tid >> 4;
    const int bp0   = ty * 4;          // 4 bpairs per thread
    const int bBase = blockIdx.x * MT;
    const int iBase = blockIdx.y * IT;

    // staging maps
    const int xj  = tid & 7;           // X: j (cells bp = xbp, xbp+16)
    const int xbp = tid >> 3;
    const int wi  = tid & 63;          // W: i (cells j = wjh + 2t)
    const int wjh = tid >> 6;

    // chunk-level LDG prefetch registers
    float xA[2][4], xB[2][4];
    float wv[4][3];

    // j-level X pipeline register sets: [set][comp][half]
    ulonglong2 xv[2][5][2];

    u64 a0[4][4], a4[4][4];            // [r][q], q = 2g+s, i = 2tx + 32g + s
    #pragma unroll
    for (int r = 0; r < 4; r++)
        #pragma unroll
        for (int q = 0; q < 4; q++) { a0[r][q] = 0ull; a4[r][q] = 0ull; }

    auto LOAD = [&](int c) {
        const int j0 = c * KJ;
        #pragma unroll
        for (int t = 0; t < 2; t++) {
            const int bp = xbp + 16 * t;
            const float* ra = x + ((size_t)(bBase + 2 * bp) * IN_DIM + (j0 + xj)) * MV;
            const float* rb = ra + (size_t)IN_DIM * MV;
            float4 a = *(const float4*)ra;
            xA[t][0] = a.x; xA[t][1] = a.y; xA[t][2] = a.z; xA[t][3] = ra[4];
            float4 b = *(const float4*)rb;
            xB[t][0] = b.x; xB[t][1] = b.y; xB[t][2] = b.z; xB[t][3] = rb[4];
        }
        #pragma unroll
        for (int t = 0; t < 4; t++) {
            const float* wr = w + ((size_t)(j0 + wjh + 2 * t) * OUT_DIM + (iBase + wi)) * MV;
            float4 q = *(const float4*)wr;
            wv[t][0] = q.x; wv[t][1] = q.y; wv[t][2] = q.z;
        }
    };

    auto STORE = [&](int buf) {
        #pragma unroll
        for (int t = 0; t < 2; t++) {
            const int bp = xbp + 16 * t;
            Xs[buf][xj][0][bp] = pack2(xA[t][0],  xB[t][0]);
            Xs[buf][xj][1][bp] = pack2(xA[t][1],  xB[t][1]);
            Xs[buf][xj][2][bp] = pack2(xA[t][2],  xB[t][2]);
            Xs[buf][xj][3][bp] = pack2(xA[t][3],  xB[t][3]);
            Xs[buf][xj][4][bp] = pack2(-xA[t][2], -xB[t][2]);
        }
        #pragma unroll
        for (int t = 0; t < 4; t++) {
            const int jj = wjh + 2 * t;
            Ws[buf][0][jj][wi] = pack2(wv[t][0], wv[t][0]);
            Ws[buf][1][jj][wi] = pack2(wv[t][1], wv[t][1]);
            Ws[buf][2][jj][wi] = pack2(wv[t][2], wv[t][2]);
        }
    };

    auto LDX = [&](int buf, int j, int set) {
        #pragma unroll
        for (int cmp = 0; cmp < 5; cmp++) {
            xv[set][cmp][0] = *(const ulonglong2*)&Xs[buf][j][cmp][bp0];
            xv[set][cmp][1] = *(const ulonglong2*)&Xs[buf][j][cmp][bp0 + 2];
        }
    };

    LOAD(0);
    STORE(0);
    __syncthreads();

    for (int c = 0; c < NCH; c++) {
        const int buf = c & 1;
        if (c + 1 < NCH) LOAD(c + 1);     // next-chunk LDG, hidden under compute

        LDX(buf, 0, 0);                   // prime X pipeline

        #pragma unroll
        for (int j = 0; j < KJ; j++) {
            const int set = j & 1;

            // W for this j: 6 LDS.128 (i-pairs 2tx / 2tx+32), all up-front
            ulonglong2 w0p[2], w1p[2], w2p[2];
            #pragma unroll
            for (int g = 0; g < 2; g++) {
                const int ib = 2 * tx + 32 * g;
                w0p[g] = *(const ulonglong2*)&Ws[buf][0][j][ib];
                w1p[g] = *(const ulonglong2*)&Ws[buf][1][j][ib];
                w2p[g] = *(const ulonglong2*)&Ws[buf][2][j][ib];
            }

            if (j + 1 < KJ) LDX(buf, j + 1, set ^ 1);   // prefetch next j's X

            #pragma unroll
            for (int g = 0; g < 2; g++) {
                #pragma unroll
                for (int r = 0; r < 4; r++) {
                    const int h  = r >> 1;
                    const int rr = r & 1;
                    const u64 x0  = rr ? xv[set][0][h].y : xv[set][0][h].x;
                    const u64 x1  = rr ? xv[set][1][h].y : xv[set][1][h].x;
                    const u64 x2  = rr ? xv[set][2][h].y : xv[set][2][h].x;
                    const u64 x4  = rr ? xv[set][3][h].y : xv[set][3][h].x;
                    const u64 x2n = rr ? xv[set][4][h].y : xv[set][4][h].x;
                    #pragma unroll
                    for (int s = 0; s < 2; s++) {
                        const int q = 2 * g + s;
                        const u64 W0 = s ? w0p[g].y : w0p[g].x;
                        const u64 W1 = s ? w1p[g].y : w1p[g].x;
                        const u64 W2 = s ? w2p[g].y : w2p[g].x;
                        a0[r][q] = fma2(x0,  W0, a0[r][q]);
                        a0[r][q] = fma2(x1,  W1, a0[r][q]);
                        a0[r][q] = fma2(x2,  W2, a0[r][q]);
                        a4[r][q] = fma2(x1,  W2, a4[r][q]);
                        a4[r][q] = fma2(x2n, W1, a4[r][q]);
                        a4[r][q] = fma2(x4,  W0, a4[r][q]);
                    }
                }
            }
        }

        if (c + 1 < NCH) STORE(buf ^ 1);
        __syncthreads();
    }

    // ---- epilogue: bias + c0/c4 into slots 0 and 4; i = 2tx + 32g + s
    #pragma unroll
    for (int g = 0; g < 2; g++) {
        #pragma unroll
        for (int s = 0; s < 2; s++) {
            const int q  = 2 * g + s;
            const int ig = iBase + 2 * tx + 32 * g + s;
            float4 blo = *(const float4*)(bias + (size_t)ig * MV);
            float4 bhi = *(const float4*)(bias + (size_t)ig * MV + 4);
            #pragma unroll
            for (int r = 0; r < 4; r++) {
                float c0e, c0o, c4e, c4o;
                unpack2(a0[r][q], c0e, c0o);
                unpack2(a4[r][q], c4e, c4o);
                const int bE = bBase + 2 * (bp0 + r);

                float4 v0 = blo; v0.x += c0e;
                float4 v1 = bhi; v1.x += c4e;
                float4* o = (float4*)(out + ((size_t)bE * OUT_DIM + ig) * MV);
                o[0] = v0; o[1] = v1;

                v0 = blo; v0.x += c0o;
                v1 = bhi; v1.x += c4o;
                o = (float4*)(out + ((size_t)(bE + 1) * OUT_DIM + ig) * MV);
                o[0] = v0; o[1] = v1;
            }
        }
    }
}

extern "C" void kernel_launch(void* const* d_in, const int* in_sizes, int n_in,
                              void* d_out, int out_size)
{
    const float* x    = (const float*)d_in[0];   // (8192, 256, 8)
    const float* w    = (const float*)d_in[1];   // (256, 256, 8)
    const float* bias = (const float*)d_in[2];   // (256, 8)
    float* out        = (float*)d_out;           // (8192, 256, 8)

    dim3 grid(B_DIM / MT, OUT_DIM / IT);         // (128, 4) = 512 CTAs
    ga_mv_kernel<<<grid, NTHR>>>(x, w, bias, out);
}

// round 12
// speedup vs baseline: 1.0987x; 1.0987x over previous
#include <cuda_runtime.h>
#include <cstdint>

// Problem constants
#define B_DIM   8192
#define IN_DIM  256
#define OUT_DIM 256
#define MV      8

// GEMM: C[8192 x 512] = A[8192 x 1024] * Wmat[1024 x 512]
//   A[b][k] = x[b][k/4][comp{0,1,2,4}[k%4]]
//   col n=2i -> y0[:,i], n=2i+1 -> y4[:,i]
#define KDIM    1024
#define NNDIM   512

#define BM      128
#define BN      64
#define KC      32
#define NCHUNK  (KDIM / KC)   // 32
#define NTHR    128           // 4 warps: (wm = w>>1) x (wn = w&1), warp tile 64x32

// smem (uint32 words): AF[buf][kstep4][wm2][mt4][lane32][reg4], BF[buf][kstep4][wn2][nt4][lane32][reg2]
#define AF_WORDS 4096          // 16 KB per buffer
#define BF_WORDS 2048          // 8 KB per buffer
#define SM_BYTES ((2 * (AF_WORDS + BF_WORDS)) * 4)   // 49152

// Wmat in fragment layout: [nblk8][chunk32][kstep4][wn2][nt4][lane32][reg2]
__device__ uint32_t g_Wfrag[NNDIM * KDIM];   // 2 MB

__device__ __forceinline__ uint32_t f2tf32(float f) {
    uint32_t u; asm("cvt.rna.tf32.f32 %0, %1;" : "=r"(u) : "f"(f)); return u;
}

// ---- Kernel 1: build W fragments from w (256,256,8) ----
__global__ void wprep_kernel(const float* __restrict__ w)
{
    const int idx = blockIdx.x * blockDim.x + threadIdx.x;   // 524288
    const int reg   = idx & 1;
    const int lane  = (idx >> 1) & 31;
    const int nt    = (idx >> 6) & 3;
    const int wn    = (idx >> 8) & 1;
    const int kstep = (idx >> 9) & 3;
    const int chunk = (idx >> 11) & 31;
    const int nblk  = idx >> 16;
    const int n = nblk * 64 + wn * 32 + nt * 8 + (lane >> 2);
    const int k = chunk * 32 + kstep * 8 + reg * 4 + (lane & 3);
    const int j = k >> 2, s = k & 3, i = n >> 1;
    const float* wr = w + ((size_t)j * OUT_DIM + i) * MV;
    float v = 0.0f;
    if ((n & 1) == 0) {
        if (s < 3) v = wr[s];                 // y0: w0,w1,w2,0
    } else {
        if (s == 1) v = wr[2];                // y4:  x1*w2
        else if (s == 2) v = -wr[1];          //     -x2*w1
        else if (s == 3) v = wr[0];           //      x4*w0
    }
    g_Wfrag[idx] = f2tf32(v);
}

// ---- Kernel 2: tf32 mma.sync GEMM + epilogue ----
__global__ void __launch_bounds__(NTHR, 2)
ga_gemm_kernel(const float* __restrict__ x,
               const float* __restrict__ bias,
               float* __restrict__ out)
{
    extern __shared__ uint32_t sm[];
    // layout: AF buf0 | AF buf1 | BF buf0 | BF buf1

    const int tid  = threadIdx.x;
    const int lane = tid & 31;
    const int wrp  = tid >> 5;
    const int wm   = wrp >> 1;       // 0..1  (M half: 64 rows)
    const int wn   = wrp & 1;        // 0..1  (N half: 32 cols)
    const int bBase = blockIdx.x * BM;
    const int nblk  = blockIdx.y;    // N block: n in [nblk*64, nblk*64+64)

    // accumulators: 4 m-tiles x 4 n-tiles x 4 f32
    float C[4][4][4];
    #pragma unroll
    for (int mt = 0; mt < 4; mt++)
        #pragma unroll
        for (int nt = 0; nt < 4; nt++)
            #pragma unroll
            for (int r = 0; r < 4; r++) C[mt][nt][r] = 0.0f;

    // staging registers
    float    vA[8][5];       // 8 (m,j) cells: x0,x1,x2,(pad),x4
    uint4    vB[4];

    // A staging map: cell p = tid + 128*t : j = p&7 (within chunk), m = p>>3
    const int aj = tid & 7;
    const int am = tid >> 3;

    auto LOAD = [&](int c) {
        #pragma unroll
        for (int t = 0; t < 8; t++) {
            const int m = am + 16 * t;
            const float* src = x + ((size_t)(bBase + m) * IN_DIM + (c * 8 + aj)) * MV;
            float4 lo = *(const float4*)src;
            vA[t][0] = lo.x; vA[t][1] = lo.y; vA[t][2] = lo.z; vA[t][3] = src[4];
        }
        const uint4* src4 = (const uint4*)(g_Wfrag + ((size_t)nblk * NCHUNK + c) * BF_WORDS);
        #pragma unroll
        for (int t = 0; t < 4; t++) vB[t] = src4[tid + NTHR * t];
    };

    auto STORE = [&](int buf) {
        uint32_t* SA = sm + buf * AF_WORDS;
        #pragma unroll
        for (int t = 0; t < 8; t++) {
            const int m = am + 16 * t;
            const int kstep = aj >> 1;
            const int wmm   = m >> 6;
            const int mt    = (m & 63) >> 4;
            const int mrow  = m & 15;
            const int reg   = 2 * (aj & 1) + (mrow >> 3);
            const int lbase = (mrow & 7) * 4;
            const int base  = (((kstep * 2 + wmm) * 4 + mt) * 32 + lbase) * 4 + reg;
            // 4 k-slots -> comps x0,x1,x2,x4 at lanes lbase..lbase+3
            SA[base +  0] = f2tf32(vA[t][0]);
            SA[base +  4] = f2tf32(vA[t][1]);
            SA[base +  8] = f2tf32(vA[t][2]);
            SA[base + 12] = f2tf32(vA[t][3]);
        }
        uint4* SB = (uint4*)(sm + 2 * AF_WORDS + buf * BF_WORDS);
        #pragma unroll
        for (int t = 0; t < 4; t++) SB[tid + NTHR * t] = vB[t];
    };

    LOAD(0);
    STORE(0);
    __syncthreads();

    for (int c = 0; c < NCHUNK; c++) {
        const int buf = c & 1;
        if (c + 1 < NCHUNK) LOAD(c + 1);

        const uint32_t* SA = sm + buf * AF_WORDS;
        const uint32_t* SB = sm + 2 * AF_WORDS + buf * BF_WORDS;

        #pragma unroll
        for (int kstep = 0; kstep < 4; kstep++) {
            uint4 a[4];
            uint2 b[4];
            #pragma unroll
            for (int mt = 0; mt < 4; mt++)
                a[mt] = *(const uint4*)&SA[(((kstep * 2 + wm) * 4 + mt) * 32 + lane) * 4];
            #pragma unroll
            for (int nt = 0; nt < 4; nt++)
                b[nt] = *(const uint2*)&SB[(((kstep * 2 + wn) * 4 + nt) * 32 + lane) * 2];
            #pragma unroll
            for (int mt = 0; mt < 4; mt++)
                #pragma unroll
                for (int nt = 0; nt < 4; nt++)
                    asm("mma.sync.aligned.m16n8k8.row.col.f32.tf32.tf32.f32 "
                        "{%0,%1,%2,%3}, {%4,%5,%6,%7}, {%8,%9}, {%0,%1,%2,%3};"
                        : "+f"(C[mt][nt][0]), "+f"(C[mt][nt][1]),
                          "+f"(C[mt][nt][2]), "+f"(C[mt][nt][3])
                        : "r"(a[mt].x), "r"(a[mt].y), "r"(a[mt].z), "r"(a[mt].w),
                          "r"(b[nt].x), "r"(b[nt].y));
        }

        if (c + 1 < NCHUNK) STORE(buf ^ 1);
        __syncthreads();
    }

    // ---- epilogue: C frags -> out; c0,c1 = (y0,y4) of i at row t/4; c2,c3 at row t/4+8
    const int iBase = nblk * 32;
    #pragma unroll
    for (int nt = 0; nt < 4; nt++) {
        const int ig = iBase + wn * 16 + nt * 4 + (lane & 3);
        float4 blo = *(const float4*)(bias + (size_t)ig * MV);
        float4 bhi = *(const float4*)(bias + (size_t)ig * MV + 4);
        #pragma unroll
        for (int mt = 0; mt < 4; mt++) {
            #pragma unroll
            for (int h = 0; h < 2; h++) {
                const int brow = bBase + wm * 64 + mt * 16 + (lane >> 2) + 8 * h;
                float4 v0 = blo; v0.x += C[mt][nt][2 * h];
                float4 v1 = bhi; v1.x += C[mt][nt][2 * h + 1];
                float4* o = (float4*)(out + ((size_t)brow * OUT_DIM + ig) * MV);
                o[0] = v0;
                o[1] = v1;
            }
        }
    }
}

extern "C" void kernel_launch(void* const* d_in, const int* in_sizes, int n_in,
                              void* d_out, int out_size)
{
    const float* x    = (const float*)d_in[0];   // (8192, 256, 8)
    const float* w    = (const float*)d_in[1];   // (256, 256, 8)
    const float* bias = (const float*)d_in[2];   // (256, 8)
    float* out        = (float*)d_out;           // (8192, 256, 8)

    static int attr_set = 0;
    if (!attr_set) {
        cudaFuncSetAttribute(ga_gemm_kernel, cudaFuncAttributeMaxDynamicSharedMemorySize,
                             SM_BYTES);
        attr_set = 1;
    }

    wprep_kernel<<<(NNDIM * KDIM) / 256, 256>>>(w);
    dim3 grid(B_DIM / BM, NNDIM / BN);           // (64, 8) = 512 CTAs
    ga_gemm_kernel<<<grid, NTHR, SM_BYTES>>>(x, bias, out);
}

// round 13
// speedup vs baseline: 1.4794x; 1.3465x over previous
#include <cuda_runtime.h>
#include <cstdint>

// Problem constants
#define B_DIM   8192
#define IN_DIM  256
#define OUT_DIM 256
#define MV      8

// GEMM: C[8192 x 512] = A[8192 x 1024] * Wmat[1024 x 512]
//   A[b][k] = x[b][k/4][comp{0,1,2,4}[k%4]]
//   col n=2i -> y0[:,i], n=2i+1 -> y4[:,i]
#define KDIM    1024
#define NNDIM   512

#define BM      128
#define BN      64
#define KC      32
#define NCHUNK  (KDIM / KC)   // 32
#define NTHR    128           // 4 warps: (wm = w>>1) x (wn = w&1), warp tile 64x32

// A fragment smem layout (words):
//   addr = kstep*1032 + (wm*4 + mt)*128 + reg*32 + lane,  lane = 4r + c
//   store: STS.128 (c contiguous), ~2-way banks; load: 4x LDS.32, 1 wf each
#define KSTRIDE  1032
#define AF_WORDS (4 * KSTRIDE)          // 4128 per buffer
#define BF_WORDS 2048                    // 8 KB per buffer
#define SM_WORDS (2 * AF_WORDS + 2 * BF_WORDS)
#define SM_BYTES (SM_WORDS * 4)          // 49408

// Wmat in fragment layout: [nblk8][chunk32][kstep4][wn2][nt4][lane32][reg2]
__device__ uint32_t g_Wfrag[NNDIM * KDIM];   // 2 MB

__device__ __forceinline__ uint32_t f2tf32(float f) {
    uint32_t u; asm("cvt.rna.tf32.f32 %0, %1;" : "=r"(u) : "f"(f)); return u;
}

// ---- Kernel 1: build W fragments from w (256,256,8) ----
__global__ void wprep_kernel(const float* __restrict__ w)
{
    const int idx = blockIdx.x * blockDim.x + threadIdx.x;   // 524288
    const int reg   = idx & 1;
    const int lane  = (idx >> 1) & 31;
    const int nt    = (idx >> 6) & 3;
    const int wn    = (idx >> 8) & 1;
    const int kstep = (idx >> 9) & 3;
    const int chunk = (idx >> 11) & 31;
    const int nblk  = idx >> 16;
    const int n = nblk * 64 + wn * 32 + nt * 8 + (lane >> 2);
    const int k = chunk * 32 + kstep * 8 + reg * 4 + (lane & 3);
    const int j = k >> 2, s = k & 3, i = n >> 1;
    const float* wr = w + ((size_t)j * OUT_DIM + i) * MV;
    float v = 0.0f;
    if ((n & 1) == 0) {
        if (s < 3) v = wr[s];                 // y0: w0,w1,w2,0
    } else {
        if (s == 1) v = wr[2];                // y4:  x1*w2
        else if (s == 2) v = -wr[1];          //     -x2*w1
        else if (s == 3) v = wr[0];           //      x4*w0
    }
    g_Wfrag[idx] = f2tf32(v);
}

// ---- Kernel 2: tf32 mma.sync GEMM + epilogue ----
__global__ void __launch_bounds__(NTHR, 2)
ga_gemm_kernel(const float* __restrict__ x,
               const float* __restrict__ bias,
               float* __restrict__ out)
{
    extern __shared__ uint32_t sm[];
    // layout: AF buf0 | AF buf1 | BF buf0 | BF buf1

    const int tid  = threadIdx.x;
    const int lane = tid & 31;
    const int wrp  = tid >> 5;
    const int wm   = wrp >> 1;       // 0..1  (M half: 64 rows)
    const int wn   = wrp & 1;        // 0..1  (N half: 32 cols)
    const int bBase = blockIdx.x * BM;
    const int nblk  = blockIdx.y;    // N block: n in [nblk*64, nblk*64+64)

    // accumulators: 4 m-tiles x 4 n-tiles x 4 f32
    float C[4][4][4];
    #pragma unroll
    for (int mt = 0; mt < 4; mt++)
        #pragma unroll
        for (int nt = 0; nt < 4; nt++)
            #pragma unroll
            for (int r = 0; r < 4; r++) C[mt][nt][r] = 0.0f;

    // staging registers
    float vA[8][4];        // 8 (m,j) cells: x0,x1,x2,x4
    uint4 vB[4];

    // A staging map: cell p = tid + 128*t : j = p&7 (within chunk), m = p>>3
    const int aj = tid & 7;
    const int am = tid >> 3;

    auto LOAD = [&](int c) {
        #pragma unroll
        for (int t = 0; t < 8; t++) {
            const int m = am + 16 * t;
            const float* src = x + ((size_t)(bBase + m) * IN_DIM + (c * 8 + aj)) * MV;
            float4 lo = *(const float4*)src;
            vA[t][0] = lo.x; vA[t][1] = lo.y; vA[t][2] = lo.z; vA[t][3] = src[4];
        }
        const uint4* src4 = (const uint4*)(g_Wfrag + ((size_t)nblk * NCHUNK + c) * BF_WORDS);
        #pragma unroll
        for (int t = 0; t < 4; t++) vB[t] = src4[tid + NTHR * t];
    };

    auto STORE = [&](int buf) {
        uint32_t* SA = sm + buf * AF_WORDS;
        const int kstep = aj >> 1;
        const int jbit  = aj & 1;
        #pragma unroll
        for (int t = 0; t < 8; t++) {
            const int m      = am + 16 * t;
            const int wmm    = m >> 6;
            const int mt     = (m >> 4) & 3;
            const int rowbit = (m >> 3) & 1;
            const int r      = m & 7;
            uint32_t* p = SA + kstep * KSTRIDE + (wmm * 4 + mt) * 128
                             + (2 * jbit + rowbit) * 32 + 4 * r;
            uint4 val;
            val.x = f2tf32(vA[t][0]);
            val.y = f2tf32(vA[t][1]);
            val.z = f2tf32(vA[t][2]);
            val.w = f2tf32(vA[t][3]);
            *(uint4*)p = val;                  // STS.128, c contiguous
        }
        uint4* SB = (uint4*)(sm + 2 * AF_WORDS + buf * BF_WORDS);
        #pragma unroll
        for (int t = 0; t < 4; t++) SB[tid + NTHR * t] = vB[t];
    };

    LOAD(0);
    STORE(0);
    __syncthreads();

    for (int c = 0; c < NCHUNK; c++) {
        const int buf = c & 1;
        if (c + 1 < NCHUNK) LOAD(c + 1);

        const uint32_t* SA = sm + buf * AF_WORDS;
        const uint32_t* SB = sm + 2 * AF_WORDS + buf * BF_WORDS;

        #pragma unroll
        for (int kstep = 0; kstep < 4; kstep++) {
            uint4 a[4];
            uint2 b[4];
            #pragma unroll
            for (int mt = 0; mt < 4; mt++) {
                const uint32_t* p = SA + kstep * KSTRIDE + (wm * 4 + mt) * 128 + lane;
                a[mt].x = p[0];        // reg0: 4 x LDS.32, each 1 wavefront
                a[mt].y = p[32];
                a[mt].z = p[64];
                a[mt].w = p[96];
            }
            #pragma unroll
            for (int nt = 0; nt < 4; nt++)
                b[nt] = *(const uint2*)&SB[(((kstep * 2 + wn) * 4 + nt) * 32 + lane) * 2];
            #pragma unroll
            for (int mt = 0; mt < 4; mt++)
                #pragma unroll
                for (int nt = 0; nt < 4; nt++)
                    asm("mma.sync.aligned.m16n8k8.row.col.f32.tf32.tf32.f32 "
                        "{%0,%1,%2,%3}, {%4,%5,%6,%7}, {%8,%9}, {%0,%1,%2,%3};"
                        : "+f"(C[mt][nt][0]), "+f"(C[mt][nt][1]),
                          "+f"(C[mt][nt][2]), "+f"(C[mt][nt][3])
                        : "r"(a[mt].x), "r"(a[mt].y), "r"(a[mt].z), "r"(a[mt].w),
                          "r"(b[nt].x), "r"(b[nt].y));
        }

        if (c + 1 < NCHUNK) STORE(buf ^ 1);
        __syncthreads();
    }

    // ---- epilogue: C frags -> out; c0,c1 = (y0,y4) of i; rows +0/+8
    const int iBase = nblk * 32;
    #pragma unroll
    for (int nt = 0; nt < 4; nt++) {
        const int ig = iBase + wn * 16 + nt * 4 + (lane & 3);
        float4 blo = *(const float4*)(bias + (size_t)ig * MV);
        float4 bhi = *(const float4*)(bias + (size_t)ig * MV + 4);
        #pragma unroll
        for (int mt = 0; mt < 4; mt++) {
            #pragma unroll
            for (int h = 0; h < 2; h++) {
                const int brow = bBase + wm * 64 + mt * 16 + (lane >> 2) + 8 * h;
                float4 v0 = blo; v0.x += C[mt][nt][2 * h];
                float4 v1 = bhi; v1.x += C[mt][nt][2 * h + 1];
                float4* o = (float4*)(out + ((size_t)brow * OUT_DIM + ig) * MV);
                o[0] = v0;
                o[1] = v1;
            }
        }
    }
}

extern "C" void kernel_launch(void* const* d_in, const int* in_sizes, int n_in,
                              void* d_out, int out_size)
{
    const float* x    = (const float*)d_in[0];   // (8192, 256, 8)
    const float* w    = (const float*)d_in[1];   // (256, 256, 8)
    const float* bias = (const float*)d_in[2];   // (256, 8)
    float* out        = (float*)d_out;           // (8192, 256, 8)

    static int attr_set = 0;
    if (!attr_set) {
        cudaFuncSetAttribute(ga_gemm_kernel, cudaFuncAttributeMaxDynamicSharedMemorySize,
                             SM_BYTES);
        attr_set = 1;
    }

    wprep_kernel<<<(NNDIM * KDIM) / 256, 256>>>(w);
    dim3 grid(B_DIM / BM, NNDIM / BN);           // (64, 8) = 512 CTAs
    ga_gemm_kernel<<<grid, NTHR, SM_BYTES>>>(x, bias, out);
}

// round 14
// speedup vs baseline: 1.9415x; 1.3124x over previous
#include <cuda_runtime.h>
#include <cstdint>

// Problem constants
#define B_DIM   8192
#define IN_DIM  256
#define OUT_DIM 256
#define MV      8

// GEMM: C[8192 x 512] = A[8192 x 1024] * Wmat[1024 x 512]
//   A[b][k] = x[b][k/4][comp{0,1,2,4}[k%4]]
//   col n=2i -> y0[:,i], n=2i+1 -> y4[:,i]
#define KDIM    1024
#define NNDIM   512

#define BM      128
#define BN      128
#define KC      32
#define NCHUNK  (KDIM / KC)   // 32
#define NTHR    256           // 8 warps: wm = wrp>>2 (2), wn = wrp&3 (4); warp tile 64x32

// A fragment smem layout (words), same as R13:
//   addr = kstep*1032 + (wm*4 + mt)*128 + reg*32 + lane
#define KSTRIDE  1032
#define AF_WORDS (4 * KSTRIDE)          // 4128 words per buffer
#define BF_WORDS 4096                    // 16 KB per buffer (two 64-col blocks)
#define SM_WORDS (2 * AF_WORDS + 2 * BF_WORDS)
#define SM_BYTES (SM_WORDS * 4)          // 65792

// Wmat fragment layout: [nblk8][chunk32][kstep4][wn2][nt4][lane32][reg2]
__device__ uint32_t g_Wfrag[NNDIM * KDIM];   // 2 MB

__device__ __forceinline__ uint32_t f2tf32(float f) {
    uint32_t u; asm("cvt.rna.tf32.f32 %0, %1;" : "=r"(u) : "f"(f)); return u;
}
__device__ __forceinline__ uint32_t smem_u32(const void* p) {
    uint32_t a;
    asm("{ .reg .u64 t; cvta.to.shared.u64 t, %1; cvt.u32.u64 %0, t; }" : "=r"(a) : "l"(p));
    return a;
}

// ---- Kernel 1: build W fragments from w (256,256,8) ----
__global__ void wprep_kernel(const float* __restrict__ w)
{
    const int idx = blockIdx.x * blockDim.x + threadIdx.x;   // 524288
    const int reg   = idx & 1;
    const int lane  = (idx >> 1) & 31;
    const int nt    = (idx >> 6) & 3;
    const int wn    = (idx >> 8) & 1;
    const int kstep = (idx >> 9) & 3;
    const int chunk = (idx >> 11) & 31;
    const int nblk  = idx >> 16;
    const int n = nblk * 64 + wn * 32 + nt * 8 + (lane >> 2);
    const int k = chunk * 32 + kstep * 8 + reg * 4 + (lane & 3);
    const int j = k >> 2, s = k & 3, i = n >> 1;
    const float* wr = w + ((size_t)j * OUT_DIM + i) * MV;
    float v = 0.0f;
    if ((n & 1) == 0) {
        if (s < 3) v = wr[s];                 // y0: w0,w1,w2,0
    } else {
        if (s == 1) v = wr[2];                // y4:  x1*w2
        else if (s == 2) v = -wr[1];          //     -x2*w1
        else if (s == 3) v = wr[0];           //      x4*w0
    }
    g_Wfrag[idx] = f2tf32(v);
}

// ---- Kernel 2: tf32 mma.sync GEMM + epilogue ----
__global__ void __launch_bounds__(NTHR, 2)
ga_gemm_kernel(const float* __restrict__ x,
               const float* __restrict__ bias,
               float* __restrict__ out)
{
    extern __shared__ uint32_t sm[];
    // layout: AF buf0 | AF buf1 | BF buf0 | BF buf1

    const int tid  = threadIdx.x;
    const int lane = tid & 31;
    const int wrp  = tid >> 5;
    const int wm   = wrp >> 2;       // 0..1  (M half: 64 rows)
    const int wn   = wrp & 3;        // 0..3  (N quarter: 32 cols)
    const int nhalf = wn >> 1;
    const int wnbit = wn & 1;
    const int bBase = blockIdx.x * BM;
    const int nblk  = blockIdx.y;    // covers n in [nblk*128, nblk*128+128)

    const uint32_t sb_bf = smem_u32(sm + 2 * AF_WORDS);

    // accumulators: 4 m-tiles x 4 n-tiles x 4 f32
    float C[4][4][4];
    #pragma unroll
    for (int mt = 0; mt < 4; mt++)
        #pragma unroll
        for (int nt = 0; nt < 4; nt++)
            #pragma unroll
            for (int r = 0; r < 4; r++) C[mt][nt][r] = 0.0f;

    // A staging: 1024 cells (128 m x 8 j), 4 per thread
    const int aj = tid & 7;
    const int am = tid >> 3;         // 0..31
    float vA[4][4];

    auto CPA_B = [&](int c, int buf) {
        const uint32_t dstb = sb_bf + buf * (BF_WORDS * 4);
        #pragma unroll
        for (int t = 0; t < 4; t++) {
            const int u = tid + NTHR * t;          // uint4 index 0..1023
            const uint32_t* src = g_Wfrag
                + ((size_t)(2 * nblk + (u >> 9)) * NCHUNK + c) * 2048 + (u & 511) * 4;
            asm volatile("cp.async.cg.shared.global [%0], [%1], 16;"
                         :: "r"(dstb + u * 16), "l"(src));
        }
        asm volatile("cp.async.commit_group;");
    };

    auto LOADA = [&](int c) {
        #pragma unroll
        for (int t = 0; t < 4; t++) {
            const int m = am + 32 * t;
            const float* src = x + ((size_t)(bBase + m) * IN_DIM + (c * 8 + aj)) * MV;
            float4 lo = *(const float4*)src;
            vA[t][0] = lo.x; vA[t][1] = lo.y; vA[t][2] = lo.z; vA[t][3] = src[4];
        }
    };

    auto STOREA = [&](int buf) {
        uint32_t* SA = sm + buf * AF_WORDS;
        const int kstep = aj >> 1;
        const int jbit  = aj & 1;
        #pragma unroll
        for (int t = 0; t < 4; t++) {
            const int m      = am + 32 * t;
            const int wmm    = m >> 6;
            const int mt     = (m >> 4) & 3;
            const int rowbit = (m >> 3) & 1;
            const int r      = m & 7;
            uint32_t* p = SA + kstep * KSTRIDE + (wmm * 4 + mt) * 128
                             + (2 * jbit + rowbit) * 32 + 4 * r;
            uint4 val;
            val.x = f2tf32(vA[t][0]);
            val.y = f2tf32(vA[t][1]);
            val.z = f2tf32(vA[t][2]);
            val.w = f2tf32(vA[t][3]);
            *(uint4*)p = val;                  // STS.128, ~2-way
        }
    };

    CPA_B(0, 0);
    LOADA(0);
    asm volatile("cp.async.wait_group 0;");
    STOREA(0);
    __syncthreads();

    for (int c = 0; c < NCHUNK; c++) {
        const int buf = c & 1;
        if (c + 1 < NCHUNK) { CPA_B(c + 1, buf ^ 1); LOADA(c + 1); }

        const uint32_t* SA = sm + buf * AF_WORDS;
        const uint32_t* SB = sm + 2 * AF_WORDS + buf * BF_WORDS + nhalf * 2048;

        #pragma unroll
        for (int kstep = 0; kstep < 4; kstep++) {
            uint2 b[4];
            #pragma unroll
            for (int nt = 0; nt < 4; nt++)
                b[nt] = *(const uint2*)&SB[(((kstep * 2 + wnbit) * 4 + nt) * 32 + lane) * 2];
            #pragma unroll
            for (int mt = 0; mt < 4; mt++) {
                const uint32_t* p = SA + kstep * KSTRIDE + (wm * 4 + mt) * 128 + lane;
                uint4 a;
                a.x = p[0];
                a.y = p[32];
                a.z = p[64];
                a.w = p[96];
                #pragma unroll
                for (int nt = 0; nt < 4; nt++)
                    asm("mma.sync.aligned.m16n8k8.row.col.f32.tf32.tf32.f32 "
                        "{%0,%1,%2,%3}, {%4,%5,%6,%7}, {%8,%9}, {%0,%1,%2,%3};"
                        : "+f"(C[mt][nt][0]), "+f"(C[mt][nt][1]),
                          "+f"(C[mt][nt][2]), "+f"(C[mt][nt][3])
                        : "r"(a.x), "r"(a.y), "r"(a.z), "r"(a.w),
                          "r"(b[nt].x), "r"(b[nt].y));
            }
        }

        if (c + 1 < NCHUNK) STOREA(buf ^ 1);
        asm volatile("cp.async.wait_group 0;");
        __syncthreads();
    }

    // ---- epilogue: C frags -> out; c0,c1 = (y0,y4) of i; rows +0/+8
    const int iBase = nblk * 64;
    #pragma unroll
    for (int nt = 0; nt < 4; nt++) {
        const int ig = iBase + wn * 16 + nt * 4 + (lane & 3);
        float4 blo = *(const float4*)(bias + (size_t)ig * MV);
        float4 bhi = *(const float4*)(bias + (size_t)ig * MV + 4);
        #pragma unroll
        for (int mt = 0; mt < 4; mt++) {
            #pragma unroll
            for (int h = 0; h < 2; h++) {
                const int brow = bBase + wm * 64 + mt * 16 + (lane >> 2) + 8 * h;
                float4 v0 = blo; v0.x += C[mt][nt][2 * h];
                float4 v1 = bhi; v1.x += C[mt][nt][2 * h + 1];
                float4* o = (float4*)(out + ((size_t)brow * OUT_DIM + ig) * MV);
                o[0] = v0;
                o[1] = v1;
            }
        }
    }
}

extern "C" void kernel_launch(void* const* d_in, const int* in_sizes, int n_in,
                              void* d_out, int out_size)
{
    const float* x    = (const float*)d_in[0];   // (8192, 256, 8)
    const float* w    = (const float*)d_in[1];   // (256, 256, 8)
    const float* bias = (const float*)d_in[2];   // (256, 8)
    float* out        = (float*)d_out;           // (8192, 256, 8)

    static int attr_set = 0;
    if (!attr_set) {
        cudaFuncSetAttribute(ga_gemm_kernel, cudaFuncAttributeMaxDynamicSharedMemorySize,
                             SM_BYTES);
        attr_set = 1;
    }

    wprep_kernel<<<(NNDIM * KDIM) / 256, 256>>>(w);
    dim3 grid(B_DIM / BM, NNDIM / BN);           // (64, 4) = 256 CTAs
    ga_gemm_kernel<<<grid, NTHR, SM_BYTES>>>(x, bias, out);
}